// round 10
// baseline (speedup 1.0000x reference)
#include <cuda_runtime.h>
#include <cuda_fp16.h>

#define NMAX   100000
#define EMAX   1600000
#define DDIM   64
#define NGR    64

// Scratch (static device globals; no allocation allowed)
__device__ float g_dis[NMAX];               // rsqrt(deg)
__device__ uint4 g_th[NMAX * 8];            // ts in fp16: 64 halves = 8 uint4 per node
__device__ float g_agg[NMAX * DDIM];        // aggregation output (fp32)
__device__ float g_pooled[NGR * DDIM];
__device__ int   g_hist[NMAX];              // in-degree histogram
__device__ int   g_off[NMAX + 1];           // CSR offsets (by dst)
__device__ int   g_cursor[NMAX];            // fill cursors
__device__ int   g_csr[EMAX];               // CSR src indices
__device__ int   g_bsum[128];               // scan block sums

// ---------------------------------------------------------------------------
// degree precompute
// ---------------------------------------------------------------------------
__global__ void k_zero_hist(int n) {
    int i = blockIdx.x * blockDim.x + threadIdx.x;
    if (i < n) g_hist[i] = 0;
}

__global__ void k_count(const int* __restrict__ dst, int E) {
    int e = blockIdx.x * blockDim.x + threadIdx.x;
    if (e < E) atomicAdd(&g_hist[dst[e]], 1);
}

// ---------------------------------------------------------------------------
// Scan level 1: per-1024 block exclusive scan; also g_dis = rsqrt(deg+1)
// ---------------------------------------------------------------------------
__global__ void __launch_bounds__(1024) k_scan1(int n) {
    __shared__ int sh[32];
    int i = blockIdx.x * 1024 + threadIdx.x;
    int lane = threadIdx.x & 31, w = threadIdx.x >> 5;
    int v = (i < n) ? g_hist[i] : 0;
    if (i < n) g_dis[i] = rsqrtf((float)(v + 1));   // fused norm
    int x = v;
    #pragma unroll
    for (int o = 1; o < 32; o <<= 1) {
        int y = __shfl_up_sync(~0u, x, o);
        if (lane >= o) x += y;
    }
    if (lane == 31) sh[w] = x;
    __syncthreads();
    if (threadIdx.x < 32) {
        int y = sh[threadIdx.x];
        #pragma unroll
        for (int o = 1; o < 32; o <<= 1) {
            int z = __shfl_up_sync(~0u, y, o);
            if (threadIdx.x >= o) y += z;
        }
        sh[threadIdx.x] = y;
    }
    __syncthreads();
    int base = (w > 0) ? sh[w - 1] : 0;
    int incl = x + base;
    if (i < n) g_off[i] = incl - v;          // exclusive within block
    if (threadIdx.x == 1023) g_bsum[blockIdx.x] = incl;
}

// ---------------------------------------------------------------------------
// Scan finalize: each block redundantly scans g_bsum (<=128 entries) in smem,
// then applies the block offset. Replaces separate scan2 + scan3 launches.
// ---------------------------------------------------------------------------
__global__ void __launch_bounds__(256) k_scanfin(int n, int E, int nb) {
    __shared__ int boff[128];
    __shared__ int sh[4];
    int t = threadIdx.x;
    int lane = t & 31, w = t >> 5;

    int v = 0, x = 0;
    if (t < 128) {
        v = (t < nb) ? g_bsum[t] : 0;
        x = v;
        #pragma unroll
        for (int o = 1; o < 32; o <<= 1) {
            int y = __shfl_up_sync(~0u, x, o);
            if (lane >= o) x += y;
        }
        if (lane == 31) sh[w] = x;
    }
    __syncthreads();
    if (t < 4) {
        int y = sh[t];
        #pragma unroll
        for (int o = 1; o < 4; o <<= 1) {
            int z = __shfl_up_sync(0xF, y, o);
            if (t >= o) y += z;
        }
        sh[t] = y;
    }
    __syncthreads();
    if (t < 128) {
        int base = (w > 0) ? sh[w - 1] : 0;
        boff[t] = x + base - v;              // exclusive scan of block sums
    }
    __syncthreads();

    int i = blockIdx.x * 256 + t;
    if (i < n) {
        int o = g_off[i] + boff[i >> 10];
        g_off[i] = o;
        g_cursor[i] = o;
    }
    if (i == 0) g_off[n] = E;
}

__global__ void k_fill(const int* __restrict__ src, const int* __restrict__ dst, int E) {
    int e = blockIdx.x * blockDim.x + threadIdx.x;
    if (e < E) {
        int pos = atomicAdd(&g_cursor[dst[e]], 1);
        g_csr[pos] = src[e];
    }
}

// ---------------------------------------------------------------------------
// SIMT GEMM (round-6 proven): ts[n][c] = fp16( dis[n] * sum_k f(in[n][k]) * W[k][c] )
//   f = relu(. + bprev) when applyPre, else identity
//   in == nullptr means read g_agg (layers 2,3)
// Block: 256 threads, 128 nodes. Each thread: 8 nodes x 4 cols.
// ---------------------------------------------------------------------------
__global__ void __launch_bounds__(256) k_gemm(
    const float* __restrict__ in, const float* __restrict__ W,
    const float* __restrict__ bprev, int applyPre, int n)
{
    __shared__ float xs[128][68];  // [node][k], pad 68 -> conflict-free stores
    __shared__ float ws[64][64];   // [k][col]
    const float* src_in = in ? in : g_agg;

    int tid = threadIdx.x;
    int node0 = blockIdx.x * 128;

    #pragma unroll
    for (int idx = tid; idx < 64 * 64; idx += 256)
        ws[idx >> 6][idx & 63] = W[idx];

    for (int idx = tid; idx < 128 * 64; idx += 256) {
        int r = idx >> 6, c = idx & 63;
        int nrow = node0 + r;
        float v = 0.0f;
        if (nrow < n) {
            v = src_in[nrow * 64 + c];
            if (applyPre) v = fmaxf(v + bprev[c], 0.0f);
        }
        xs[r][c] = v;
    }
    __syncthreads();

    int c4 = tid & 15;      // column group: cols [4*c4, 4*c4+3]
    int g  = tid >> 4;      // node group:   nodes [8*g, 8*g+7] within tile
    float4 acc[8];
    #pragma unroll
    for (int j = 0; j < 8; j++) acc[j] = make_float4(0.f, 0.f, 0.f, 0.f);

    #pragma unroll 4
    for (int k = 0; k < 64; k++) {
        float4 w4 = *reinterpret_cast<const float4*>(&ws[k][c4 * 4]);
        #pragma unroll
        for (int j = 0; j < 8; j++) {
            float xv = xs[g * 8 + j][k];
            acc[j].x += xv * w4.x;
            acc[j].y += xv * w4.y;
            acc[j].z += xv * w4.z;
            acc[j].w += xv * w4.w;
        }
    }

    #pragma unroll
    for (int j = 0; j < 8; j++) {
        int nrow = node0 + g * 8 + j;
        if (nrow < n) {
            float d = g_dis[nrow];
            __half2 h0 = __floats2half2_rn(acc[j].x * d, acc[j].y * d);
            __half2 h1 = __floats2half2_rn(acc[j].z * d, acc[j].w * d);
            uint2 u;
            u.x = *reinterpret_cast<unsigned*>(&h0);
            u.y = *reinterpret_cast<unsigned*>(&h1);
            reinterpret_cast<uint2*>(g_th)[nrow * 16 + c4] = u;
        }
    }
}

// ---------------------------------------------------------------------------
// Aggregation (gather, no atomics, fp16 messages, fp32 accumulate):
//   acc = ts[i] + sum_{j in CSR[i]} ts[j];   out = dis[i] * acc
// Layers 1,2: write g_agg.
// Layer 3 (doPool): pooled[batch[i]] += relu(out + b3)  via red.global.v4.
// 8 lanes per node (one uint4 = 8 halves each). 4 nodes/warp, 32/block.
// ---------------------------------------------------------------------------
__device__ __forceinline__ void addh8(float* acc, uint4 v) {
    const __half2* h = reinterpret_cast<const __half2*>(&v);
    float2 f0 = __half22float2(h[0]);
    float2 f1 = __half22float2(h[1]);
    float2 f2 = __half22float2(h[2]);
    float2 f3 = __half22float2(h[3]);
    acc[0] += f0.x; acc[1] += f0.y;
    acc[2] += f1.x; acc[3] += f1.y;
    acc[4] += f2.x; acc[5] += f2.y;
    acc[6] += f3.x; acc[7] += f3.y;
}

__global__ void __launch_bounds__(256) k_agg(
    int n, int doPool, const int* __restrict__ batch, const float* __restrict__ b3)
{
    int tid = threadIdx.x;
    int lane = tid & 31;
    int warp = tid >> 5;
    int node = blockIdx.x * 32 + warp * 4 + (lane >> 3);
    int s = lane & 7;
    if (node >= n) return;

    float acc[8];
    #pragma unroll
    for (int q = 0; q < 8; q++) acc[q] = 0.0f;

    addh8(acc, g_th[node * 8 + s]);     // self loop (ts already has dis[self])

    int beg = g_off[node];
    int end = g_off[node + 1];
    int j = beg;
    for (; j + 4 <= end; j += 4) {
        int s0 = g_csr[j], s1 = g_csr[j + 1], s2 = g_csr[j + 2], s3 = g_csr[j + 3];
        uint4 v0 = g_th[s0 * 8 + s];
        uint4 v1 = g_th[s1 * 8 + s];
        uint4 v2 = g_th[s2 * 8 + s];
        uint4 v3 = g_th[s3 * 8 + s];
        addh8(acc, v0); addh8(acc, v1); addh8(acc, v2); addh8(acc, v3);
    }
    for (; j < end; j++)
        addh8(acc, g_th[g_csr[j] * 8 + s]);

    float d = g_dis[node];
    #pragma unroll
    for (int q = 0; q < 8; q++) acc[q] *= d;

    if (doPool) {
        int gph = batch[node];
        const float4* b4 = reinterpret_cast<const float4*>(b3);
        float4 ba = b4[s * 2], bb = b4[s * 2 + 1];
        float4 r0 = make_float4(fmaxf(acc[0] + ba.x, 0.f), fmaxf(acc[1] + ba.y, 0.f),
                                fmaxf(acc[2] + ba.z, 0.f), fmaxf(acc[3] + ba.w, 0.f));
        float4 r1 = make_float4(fmaxf(acc[4] + bb.x, 0.f), fmaxf(acc[5] + bb.y, 0.f),
                                fmaxf(acc[6] + bb.z, 0.f), fmaxf(acc[7] + bb.w, 0.f));
        float* p = &g_pooled[gph * 64 + s * 8];
        asm volatile("red.global.add.v4.f32 [%0], {%1,%2,%3,%4};"
                     :: "l"(p), "f"(r0.x), "f"(r0.y), "f"(r0.z), "f"(r0.w) : "memory");
        asm volatile("red.global.add.v4.f32 [%0], {%1,%2,%3,%4};"
                     :: "l"(p + 4), "f"(r1.x), "f"(r1.y), "f"(r1.z), "f"(r1.w) : "memory");
    } else {
        float4 o0 = make_float4(acc[0], acc[1], acc[2], acc[3]);
        float4 o1 = make_float4(acc[4], acc[5], acc[6], acc[7]);
        float4* out = reinterpret_cast<float4*>(&g_agg[node * 64 + s * 8]);
        out[0] = o0;
        out[1] = o1;
    }
}

// ---------------------------------------------------------------------------
__global__ void k_zero_pooled() {
    int i = blockIdx.x * blockDim.x + threadIdx.x;
    if (i < NGR * DDIM) g_pooled[i] = 0.0f;
}

__global__ void k_final(const float* __restrict__ lw, const float* __restrict__ lb,
                        float* __restrict__ out) {
    int g = threadIdx.x;   // 64 threads
    float s = lb[0];
    #pragma unroll
    for (int c = 0; c < 64; c++)
        s += g_pooled[g * 64 + c] * lw[c];
    out[g] = s;
}

// ---------------------------------------------------------------------------
extern "C" void kernel_launch(void* const* d_in, const int* in_sizes, int n_in,
                              void* d_out, int out_size) {
    const float* x  = (const float*)d_in[0];
    const int*   ei = (const int*)  d_in[1];
    const int*   batch = (const int*)d_in[2];
    const float* W1 = (const float*)d_in[3];
    const float* b1 = (const float*)d_in[4];
    const float* W2 = (const float*)d_in[5];
    const float* b2 = (const float*)d_in[6];
    const float* W3 = (const float*)d_in[7];
    const float* b3 = (const float*)d_in[8];
    const float* lw = (const float*)d_in[9];
    const float* lb = (const float*)d_in[10];
    float* out = (float*)d_out;

    int n = in_sizes[0] / DDIM;
    int E = in_sizes[1] / 2;
    const int* src = ei;
    const int* dst = ei + E;

    // degree + normalization + CSR build
    k_zero_hist<<<(n + 255) / 256, 256>>>(n);
    k_count<<<(E + 255) / 256, 256>>>(dst, E);
    int nb = (n + 1023) / 1024;
    k_scan1<<<nb, 1024>>>(n);
    k_scanfin<<<(n + 255) / 256, 256>>>(n, E, nb);
    k_fill<<<(E + 255) / 256, 256>>>(src, dst, E);
    k_zero_pooled<<<(NGR * DDIM + 255) / 256, 256>>>();   // before layer-3 agg

    int gemmBlocks = (n + 127) / 128;
    int aggBlocks  = (n + 31) / 32;

    // layer 1
    k_gemm<<<gemmBlocks, 256>>>(x, W1, nullptr, 0, n);
    k_agg<<<aggBlocks, 256>>>(n, 0, nullptr, nullptr);
    // layer 2 (bias+relu of layer 1 fused into GEMM input read)
    k_gemm<<<gemmBlocks, 256>>>(nullptr, W2, b1, 1, n);
    k_agg<<<aggBlocks, 256>>>(n, 0, nullptr, nullptr);
    // layer 3: agg fuses relu(+b3) and pooling
    k_gemm<<<gemmBlocks, 256>>>(nullptr, W3, b2, 1, n);
    k_agg<<<aggBlocks, 256>>>(n, 1, batch, b3);

    // final linear
    k_final<<<1, NGR>>>(lw, lb, out);
}

// round 13
// speedup vs baseline: 1.3896x; 1.3896x over previous
#include <cuda_runtime.h>
#include <cuda_fp16.h>
#include <mma.h>
using namespace nvcuda;

#define NMAX   100000
#define EMAX   1600000
#define DDIM   64
#define NGR    64

// Scratch (static device globals; no allocation allowed)
__device__ float g_dis[NMAX];               // rsqrt(deg)
__device__ uint4 g_th[NMAX * 8];            // ts in fp16: 64 halves = 8 uint4 per node
__device__ float g_agg[NMAX * DDIM];        // aggregation output (fp32)
__device__ float g_pooled[NGR * DDIM];
__device__ int   g_hist[NMAX];              // in-degree histogram
__device__ int   g_off[NMAX + 1];           // CSR offsets (by dst)
__device__ int   g_cursor[NMAX];            // fill cursors
__device__ int   g_csr[EMAX];               // CSR src indices
__device__ int   g_bsum[128];               // scan block sums

// ---------------------------------------------------------------------------
// degree precompute
// ---------------------------------------------------------------------------
__global__ void k_zero_hist(int n) {
    int i = blockIdx.x * blockDim.x + threadIdx.x;
    if (i < n) g_hist[i] = 0;
}

__global__ void k_count(const int* __restrict__ dst, int E) {
    int e = blockIdx.x * blockDim.x + threadIdx.x;
    if (e < E) atomicAdd(&g_hist[dst[e]], 1);
}

// ---------------------------------------------------------------------------
// Scan level 1: per-1024 block exclusive scan; also g_dis = rsqrt(deg+1)
// ---------------------------------------------------------------------------
__global__ void __launch_bounds__(1024) k_scan1(int n) {
    __shared__ int sh[32];
    int i = blockIdx.x * 1024 + threadIdx.x;
    int lane = threadIdx.x & 31, w = threadIdx.x >> 5;
    int v = (i < n) ? g_hist[i] : 0;
    if (i < n) g_dis[i] = rsqrtf((float)(v + 1));   // fused norm
    int x = v;
    #pragma unroll
    for (int o = 1; o < 32; o <<= 1) {
        int y = __shfl_up_sync(~0u, x, o);
        if (lane >= o) x += y;
    }
    if (lane == 31) sh[w] = x;
    __syncthreads();
    if (threadIdx.x < 32) {
        int y = sh[threadIdx.x];
        #pragma unroll
        for (int o = 1; o < 32; o <<= 1) {
            int z = __shfl_up_sync(~0u, y, o);
            if (threadIdx.x >= o) y += z;
        }
        sh[threadIdx.x] = y;
    }
    __syncthreads();
    int base = (w > 0) ? sh[w - 1] : 0;
    int incl = x + base;
    if (i < n) g_off[i] = incl - v;          // exclusive within block
    if (threadIdx.x == 1023) g_bsum[blockIdx.x] = incl;
}

// ---------------------------------------------------------------------------
// Scan finalize: each block redundantly scans g_bsum (<=128 entries) in smem,
// then applies the block offset. Block 0 also zeroes g_pooled.
// ---------------------------------------------------------------------------
__global__ void __launch_bounds__(256) k_scanfin(int n, int E, int nb) {
    __shared__ int boff[128];
    __shared__ int sh[4];
    int t = threadIdx.x;
    int lane = t & 31, w = t >> 5;

    if (blockIdx.x == 0) {
        #pragma unroll
        for (int q = 0; q < NGR * DDIM / 256; q++)
            g_pooled[q * 256 + t] = 0.0f;
    }

    int v = 0, x = 0;
    if (t < 128) {
        v = (t < nb) ? g_bsum[t] : 0;
        x = v;
        #pragma unroll
        for (int o = 1; o < 32; o <<= 1) {
            int y = __shfl_up_sync(~0u, x, o);
            if (lane >= o) x += y;
        }
        if (lane == 31) sh[w] = x;
    }
    __syncthreads();
    if (t < 4) {
        int y = sh[t];
        #pragma unroll
        for (int o = 1; o < 4; o <<= 1) {
            int z = __shfl_up_sync(0xF, y, o);
            if (t >= o) y += z;
        }
        sh[t] = y;
    }
    __syncthreads();
    if (t < 128) {
        int base = (w > 0) ? sh[w - 1] : 0;
        boff[t] = x + base - v;              // exclusive scan of block sums
    }
    __syncthreads();

    int i = blockIdx.x * 256 + t;
    if (i < n) {
        int o = g_off[i] + boff[i >> 10];
        g_off[i] = o;
        g_cursor[i] = o;
    }
    if (i == 0) g_off[n] = E;
}

__global__ void k_fill(const int* __restrict__ src, const int* __restrict__ dst, int E) {
    int e = blockIdx.x * blockDim.x + threadIdx.x;
    if (e < E) {
        int pos = atomicAdd(&g_cursor[dst[e]], 1);
        g_csr[pos] = src[e];
    }
}

// ---------------------------------------------------------------------------
// Tensor-core GEMM (round-9, measured -16us vs SIMT):
//   ts[n][c] = fp16( dis[n] * sum_k f(in[n][k]) * W[k][c] )
//   f = relu(. + bprev) when applyPre, else identity
//   in == nullptr means read g_agg (layers 2,3)
// Block: 256 threads = 8 warps, 128 nodes. Warp w: rows [16w,16w+16).
// wmma m16n16k16, fp16 operands, fp32 accumulate.
// ---------------------------------------------------------------------------
#define XS_LD 72
#define AC_LD 68
#define SM_XS_BYTES (128 * XS_LD * 2)            // 18432
#define SM_WS_BYTES (64 * XS_LD * 2)             //  9216
#define SM_ACC_BYTES (8 * 16 * AC_LD * 4)        // 34816
#define SM_TOTAL (SM_ACC_BYTES > (SM_XS_BYTES + SM_WS_BYTES) ? SM_ACC_BYTES : (SM_XS_BYTES + SM_WS_BYTES))

__global__ void __launch_bounds__(256) k_gemm(
    const float* __restrict__ in, const float* __restrict__ W,
    const float* __restrict__ bprev, int applyPre, int n)
{
    __shared__ __align__(32) char smbuf[SM_TOTAL];
    __half (*xs)[XS_LD] = reinterpret_cast<__half(*)[XS_LD]>(smbuf);
    __half (*ws)[XS_LD] = reinterpret_cast<__half(*)[XS_LD]>(smbuf + SM_XS_BYTES);

    const float* src_in = in ? in : g_agg;
    int tid = threadIdx.x;
    int warp = tid >> 5;
    int node0 = blockIdx.x * 128;

    // stage W (64x64) as fp16
    for (int idx = tid; idx < 64 * 64; idx += 256)
        ws[idx >> 6][idx & 63] = __float2half_rn(W[idx]);

    // stage X (128x64) as fp16, with optional relu(.+bprev)
    for (int idx = tid; idx < 128 * 64; idx += 256) {
        int r = idx >> 6, c = idx & 63;
        int nrow = node0 + r;
        float v = 0.0f;
        if (nrow < n) {
            v = src_in[nrow * 64 + c];
            if (applyPre) v = fmaxf(v + bprev[c], 0.0f);
        }
        xs[r][c] = __float2half_rn(v);
    }
    __syncthreads();

    wmma::fragment<wmma::matrix_a, 16, 16, 16, __half, wmma::row_major> fa;
    wmma::fragment<wmma::matrix_b, 16, 16, 16, __half, wmma::row_major> fb;
    wmma::fragment<wmma::accumulator, 16, 16, 16, float> facc[4];
    #pragma unroll
    for (int n0 = 0; n0 < 4; n0++) wmma::fill_fragment(facc[n0], 0.0f);

    #pragma unroll
    for (int k0 = 0; k0 < 4; k0++) {
        wmma::load_matrix_sync(fa, &xs[warp * 16][k0 * 16], XS_LD);
        #pragma unroll
        for (int n0 = 0; n0 < 4; n0++) {
            wmma::load_matrix_sync(fb, &ws[k0 * 16][n0 * 16], XS_LD);
            wmma::mma_sync(facc[n0], fa, fb, facc[n0]);
        }
    }

    __syncthreads();   // everyone done reading xs/ws; reuse smem for acc

    float (*accb)[AC_LD] = reinterpret_cast<float(*)[AC_LD]>(smbuf + warp * 16 * AC_LD * 4);
    #pragma unroll
    for (int n0 = 0; n0 < 4; n0++)
        wmma::store_matrix_sync(&accb[0][n0 * 16], facc[n0], AC_LD, wmma::mem_row_major);
    __syncwarp();

    // epilogue: scale by dis, convert to fp16, write g_th
    int lane = tid & 31;
    int row = lane >> 1;                 // 0..15
    int sbase = (lane & 1) * 4;          // uint4 slots [sbase, sbase+4)
    int nrow = node0 + warp * 16 + row;
    if (nrow < n) {
        float d = g_dis[nrow];
        #pragma unroll
        for (int s = 0; s < 4; s++) {
            int c0 = (sbase + s) * 8;
            __half2 h0 = __floats2half2_rn(accb[row][c0 + 0] * d, accb[row][c0 + 1] * d);
            __half2 h1 = __floats2half2_rn(accb[row][c0 + 2] * d, accb[row][c0 + 3] * d);
            __half2 h2 = __floats2half2_rn(accb[row][c0 + 4] * d, accb[row][c0 + 5] * d);
            __half2 h3 = __floats2half2_rn(accb[row][c0 + 6] * d, accb[row][c0 + 7] * d);
            uint4 u;
            u.x = *reinterpret_cast<unsigned*>(&h0);
            u.y = *reinterpret_cast<unsigned*>(&h1);
            u.z = *reinterpret_cast<unsigned*>(&h2);
            u.w = *reinterpret_cast<unsigned*>(&h3);
            g_th[nrow * 8 + sbase + s] = u;
        }
    }
}

// ---------------------------------------------------------------------------
// Aggregation (round-6 proven; gather, no atomics, fp16 msgs, fp32 accum):
//   agg[i] = dis[i] * ( ts[i] + sum_{j in CSR[i]} ts[j] )
// 8 lanes per node (one uint4 = 8 halves each). 4 nodes/warp, 32/block.
// ---------------------------------------------------------------------------
__device__ __forceinline__ void addh8(float* acc, uint4 v) {
    const __half2* h = reinterpret_cast<const __half2*>(&v);
    float2 f0 = __half22float2(h[0]);
    float2 f1 = __half22float2(h[1]);
    float2 f2 = __half22float2(h[2]);
    float2 f3 = __half22float2(h[3]);
    acc[0] += f0.x; acc[1] += f0.y;
    acc[2] += f1.x; acc[3] += f1.y;
    acc[4] += f2.x; acc[5] += f2.y;
    acc[6] += f3.x; acc[7] += f3.y;
}

__global__ void __launch_bounds__(256) k_agg(int n) {
    int tid = threadIdx.x;
    int lane = tid & 31;
    int warp = tid >> 5;
    int node = blockIdx.x * 32 + warp * 4 + (lane >> 3);
    int s = lane & 7;
    if (node >= n) return;

    float acc[8];
    #pragma unroll
    for (int q = 0; q < 8; q++) acc[q] = 0.0f;

    addh8(acc, g_th[node * 8 + s]);     // self loop (ts already has dis[self])

    int beg = g_off[node];
    int end = g_off[node + 1];
    int j = beg;
    for (; j + 4 <= end; j += 4) {
        int s0 = g_csr[j], s1 = g_csr[j + 1], s2 = g_csr[j + 2], s3 = g_csr[j + 3];
        uint4 v0 = g_th[s0 * 8 + s];
        uint4 v1 = g_th[s1 * 8 + s];
        uint4 v2 = g_th[s2 * 8 + s];
        uint4 v3 = g_th[s3 * 8 + s];
        addh8(acc, v0); addh8(acc, v1); addh8(acc, v2); addh8(acc, v3);
    }
    for (; j < end; j++)
        addh8(acc, g_th[g_csr[j] * 8 + s]);

    float d = g_dis[node];
    float4 o0 = make_float4(acc[0] * d, acc[1] * d, acc[2] * d, acc[3] * d);
    float4 o1 = make_float4(acc[4] * d, acc[5] * d, acc[6] * d, acc[7] * d);
    float4* out = reinterpret_cast<float4*>(&g_agg[node * 64 + s * 8]);
    out[0] = o0;
    out[1] = o1;
}

// ---------------------------------------------------------------------------
// Pool (round-6 proven): pooled[batch[i]] += relu(agg[i] + b3);
// batch sorted -> per-thread run-length accumulation, flush on graph change.
// ---------------------------------------------------------------------------
__device__ __forceinline__ void pool_flush(int gph, int s, float4 sum) {
    float* p = &g_pooled[gph * 64 + s * 4];
    asm volatile("red.global.add.v4.f32 [%0], {%1,%2,%3,%4};"
                 :: "l"(p), "f"(sum.x), "f"(sum.y), "f"(sum.z), "f"(sum.w)
                 : "memory");
}

__global__ void k_pool(const int* __restrict__ batch, const float* __restrict__ b3, int n) {
    int tid = threadIdx.x;
    int s = tid & 15;
    int chunk = tid >> 4;
    int n0 = blockIdx.x * 256 + chunk * 16;
    float4 b4 = reinterpret_cast<const float4*>(b3)[s];

    float4 sum = make_float4(0.f, 0.f, 0.f, 0.f);
    int cur = -1;
    for (int j = 0; j < 16; j++) {
        int nn = n0 + j;
        if (nn >= n) break;
        int gph = batch[nn];
        if (gph != cur) {
            if (cur >= 0) pool_flush(cur, s, sum);
            cur = gph;
            sum = make_float4(0.f, 0.f, 0.f, 0.f);
        }
        float4 v = reinterpret_cast<const float4*>(g_agg)[nn * 16 + s];
        sum.x += fmaxf(v.x + b4.x, 0.0f);
        sum.y += fmaxf(v.y + b4.y, 0.0f);
        sum.z += fmaxf(v.z + b4.z, 0.0f);
        sum.w += fmaxf(v.w + b4.w, 0.0f);
    }
    if (cur >= 0) pool_flush(cur, s, sum);
}

__global__ void k_final(const float* __restrict__ lw, const float* __restrict__ lb,
                        float* __restrict__ out) {
    int g = threadIdx.x;   // 64 threads
    float s = lb[0];
    #pragma unroll
    for (int c = 0; c < 64; c++)
        s += g_pooled[g * 64 + c] * lw[c];
    out[g] = s;
}

// ---------------------------------------------------------------------------
extern "C" void kernel_launch(void* const* d_in, const int* in_sizes, int n_in,
                              void* d_out, int out_size) {
    const float* x  = (const float*)d_in[0];
    const int*   ei = (const int*)  d_in[1];
    const int*   batch = (const int*)d_in[2];
    const float* W1 = (const float*)d_in[3];
    const float* b1 = (const float*)d_in[4];
    const float* W2 = (const float*)d_in[5];
    const float* b2 = (const float*)d_in[6];
    const float* W3 = (const float*)d_in[7];
    const float* b3 = (const float*)d_in[8];
    const float* lw = (const float*)d_in[9];
    const float* lb = (const float*)d_in[10];
    float* out = (float*)d_out;

    int n = in_sizes[0] / DDIM;
    int E = in_sizes[1] / 2;
    const int* src = ei;
    const int* dst = ei + E;

    // degree + normalization + CSR build (scanfin also zeroes g_pooled)
    k_zero_hist<<<(n + 255) / 256, 256>>>(n);
    k_count<<<(E + 255) / 256, 256>>>(dst, E);
    int nb = (n + 1023) / 1024;
    k_scan1<<<nb, 1024>>>(n);
    k_scanfin<<<(n + 255) / 256, 256>>>(n, E, nb);
    k_fill<<<(E + 255) / 256, 256>>>(src, dst, E);

    int gemmBlocks = (n + 127) / 128;
    int aggBlocks  = (n + 31) / 32;

    // layer 1
    k_gemm<<<gemmBlocks, 256>>>(x, W1, nullptr, 0, n);
    k_agg<<<aggBlocks, 256>>>(n);
    // layer 2 (bias+relu of layer 1 fused into GEMM input read)
    k_gemm<<<gemmBlocks, 256>>>(nullptr, W2, b1, 1, n);
    k_agg<<<aggBlocks, 256>>>(n);
    // layer 3
    k_gemm<<<gemmBlocks, 256>>>(nullptr, W3, b2, 1, n);
    k_agg<<<aggBlocks, 256>>>(n);

    // pool (bias+relu of layer 3 fused) + final linear
    k_pool<<<(n + 255) / 256, 256>>>(batch, b3, n);
    k_final<<<1, NGR>>>(lw, lb, out);
}